// round 17
// baseline (speedup 1.0000x reference)
#include <cuda_runtime.h>

#define FULLMASK 0xFFFFFFFFu
#define KNN 16
#define GB 128                       // bins per axis
#define NB2 (GB * GB)                // 16384
#define XLO (-6.0f)
#define BINW (12.0f / 128.0f)
#define BSCALE (128.0f / 12.0f)
#define NCAP 32768
#define RBIG 3.0e38f
#define TPQ 4                        // threads per query
#define PRIMEW (TPQ * KNN)           // 64-slot prime window

// ---- global scratch (no allocation; zero-initialized at module load) ----
// Self-cleaning: prefix_kernel re-zeros g_hist, hist_kernel re-zeros g_cnt.
__device__ __align__(16) int g_hist[NB2];
__device__ __align__(16) int g_cnt[NB2];
__device__ __align__(16) int g_binstart[NB2 + 1];
__device__ __align__(16) float2 g_sxy[NCAP];
__device__ int g_sorig[NCAP];

static __device__ __forceinline__ int bin1(float v) {
    int b = (int)((v - XLO) * BSCALE);
    return min(max(b, 0), GB - 1);
}

// ================= setup kernels =================
__global__ void __launch_bounds__(128, 1)
hist_kernel(const float* __restrict__ p, int n) {
    int i = blockIdx.x * blockDim.x + threadIdx.x;
    // zero g_cnt for the scatter that follows (and for graph replays)
    if (i < NB2 / 4) reinterpret_cast<int4*>(g_cnt)[i] = make_int4(0, 0, 0, 0);
    if (i < n) {
        float x = p[3 * i];
        float y = p[3 * i + 1];
        atomicAdd(&g_hist[(bin1(y) << 7) | bin1(x)], 1);
    }
}

__global__ void __launch_bounds__(1024, 1)
prefix_kernel() {
    __shared__ int wsum[32];
    const int tid = threadIdx.x;
    const int lane = tid & 31;
    const int wid = tid >> 5;
    int4* h4 = reinterpret_cast<int4*>(g_hist);

    int s = 0;
#pragma unroll
    for (int j = 0; j < 4; j++) {
        int4 v = h4[tid * 4 + j];
        s += v.x + v.y + v.z + v.w;
    }
    int x = s;
#pragma unroll
    for (int d = 1; d < 32; d <<= 1) {
        int y = __shfl_up_sync(FULLMASK, x, d);
        if (lane >= d) x += y;
    }
    if (lane == 31) wsum[wid] = x;
    __syncthreads();
    if (tid < 32) {
        int w = wsum[tid];
#pragma unroll
        for (int d = 1; d < 32; d <<= 1) {
            int y = __shfl_up_sync(FULLMASK, w, d);
            if (tid >= d) w += y;
        }
        wsum[tid] = w;
    }
    __syncthreads();
    int run = x - s + (wid ? wsum[wid - 1] : 0);
    const int4 z4 = make_int4(0, 0, 0, 0);
#pragma unroll
    for (int j = 0; j < 4; j++) {
        int4 v = h4[tid * 4 + j];
        int4 o;
        o.x = run;
        o.y = run + v.x;
        o.z = run + v.x + v.y;
        o.w = run + v.x + v.y + v.z;
        reinterpret_cast<int4*>(g_binstart)[tid * 4 + j] = o;
        h4[tid * 4 + j] = z4;           // self-clean
        run += v.x + v.y + v.z + v.w;
    }
    if (tid == 1023) g_binstart[NB2] = run;
}

__global__ void __launch_bounds__(128, 1)
scatter_kernel(const float* __restrict__ p, int n) {
    int i = blockIdx.x * blockDim.x + threadIdx.x;
    if (i < n) {
        float x = p[3 * i];
        float y = p[3 * i + 1];
        int key = (bin1(y) << 7) | bin1(x);
        int pos = g_binstart[key] + atomicAdd(&g_cnt[key], 1);
        g_sxy[pos] = make_float2(x, y);
        g_sorig[pos] = i;
    }
}

// merge TPQ=4 per-thread sorted ascending DISJOINT lists into union top-16
static __device__ __forceinline__ void merge4(float kn[KNN], unsigned gmask) {
#pragma unroll
    for (int step = 1; step <= 2; step <<= 1) {
        float m2[KNN];
#pragma unroll
        for (int i = 0; i < KNN; i++) {
            float b = __shfl_xor_sync(gmask, kn[KNN - 1 - i], step);
            m2[i] = fminf(kn[i], b);  // bitonic sequence of union's 16 smallest
        }
#pragma unroll
        for (int j = 8; j > 0; j >>= 1) {
#pragma unroll
            for (int i = 0; i < 16; i++) {
                if (!(i & j)) {
                    float mn = fminf(m2[i], m2[i | j]);
                    float mx = fmaxf(m2[i], m2[i | j]);
                    m2[i] = mn;
                    m2[i | j] = mx;
                }
            }
        }
#pragma unroll
        for (int i = 0; i < KNN; i++) kn[i] = m2[i];
    }
}

// ================= main kernel: 4 threads/query, single-pass rows ===========
__global__ void __launch_bounds__(128, 1)
knn4_kernel(float* __restrict__ out, int n) {
    const int t = blockIdx.x * 128 + threadIdx.x;
    const int s = t >> 2;          // query slot
    const int sub = t & 3;         // group member 0..3
    if (s >= n) return;
    const unsigned gmask = 0xFu << (threadIdx.x & 28);

    const float2 q = __ldg(&g_sxy[s]);
    const float xq = q.x;
    const float yq = q.y;

    // ---- prime: window of 64 slots, 16 per thread (stride 4) ----
    const int W = min(max(s - PRIMEW / 2, 0), n - PRIMEW);
    float kn[KNN];
#pragma unroll
    for (int j = 0; j < KNN; j++) {
        int c = W + TPQ * j + sub;
        float2 v = __ldg(&g_sxy[c]);
        float dx = xq - v.x;
        float dy = yq - v.y;
        float d2 = fmaf(dx, dx, dy * dy);
        kn[j] = (c == s) ? RBIG : d2;
    }
    // full bitonic sort of 16 registers (static network)
#pragma unroll
    for (int k = 2; k <= 16; k <<= 1) {
#pragma unroll
        for (int j = k >> 1; j > 0; j >>= 1) {
#pragma unroll
            for (int i = 0; i < 16; i++) {
                int l = i ^ j;
                if (l > i) {
                    bool up = ((i & k) == 0);
                    float mn = fminf(kn[i], kn[l]);
                    float mx = fmaxf(kn[i], kn[l]);
                    kn[i] = up ? mn : mx;
                    kn[l] = up ? mx : mn;
                }
            }
        }
    }
    float kn15 = kn[KNN - 1];

#define TRY_INSERT(D2, GATE)                                          \
    if ((D2) < (GATE)) {                                              \
        float v = (D2);                                               \
        _Pragma("unroll")                                             \
        for (int i = 0; i < KNN; i++) {                               \
            float lo = fminf(kn[i], v);                               \
            v = fmaxf(kn[i], v);                                      \
            kn[i] = lo;                                               \
        }                                                             \
        kn15 = kn[KNN - 1];                                           \
    }

    // ---- cheap valid bound on the union's 16th-smallest:
    //   {kn[0..3]} x 4 threads = 16 distinct real candidates
    //   => max_i(kn[3]) >= union 16th.  min_i(kn15) also valid. ----
    float kng;
    {
        float b4 = kn[3];
        b4 = fmaxf(b4, __shfl_xor_sync(gmask, b4, 1));
        b4 = fmaxf(b4, __shfl_xor_sync(gmask, b4, 2));
        float b16 = kn15;
        b16 = fminf(b16, __shfl_xor_sync(gmask, b16, 1));
        b16 = fminf(b16, __shfl_xor_sync(gmask, b16, 2));
        kng = fminf(b4, b16);
    }
    const float rad = sqrtf(kng) * 1.0001f + 1e-7f;

    // ---- phase B: single pass over the covered bin rectangle ----
    // all true neighbors lie within rad of q (kng >= true 16th d^2), so the
    // rectangle [yq-rad, yq+rad] x [xq-rad, xq+rad] covers them all.
    auto scan_span = [&](int lo, int hi) {
        int c = lo + sub;
        for (; c + TPQ < hi; c += 2 * TPQ) {
            float2 v0 = __ldg(&g_sxy[c]);
            float2 v1 = __ldg(&g_sxy[c + TPQ]);
            float dx0 = xq - v0.x, dy0 = yq - v0.y;
            float dx1 = xq - v1.x, dy1 = yq - v1.y;
            float d20 = fmaf(dx0, dx0, dy0 * dy0);
            float d21 = fmaf(dx1, dx1, dy1 * dy1);
            float gate = fminf(kn15, kng);
            TRY_INSERT(d20, gate);
            gate = fminf(kn15, kng);
            TRY_INSERT(d21, gate);
        }
        if (c < hi) {
            float2 v = __ldg(&g_sxy[c]);
            float dx = xq - v.x, dy = yq - v.y;
            float d2 = fmaf(dx, dx, dy * dy);
            float gate = fminf(kn15, kng);
            TRY_INSERT(d2, gate);
        }
    };

    const int bylo = bin1(yq - rad), byhi = bin1(yq + rad);
    const int bxlo = bin1(xq - rad), bxhi = bin1(xq + rad);

    int lo = __ldg(&g_binstart[(bylo << 7) + bxlo]);
    int hi = __ldg(&g_binstart[(bylo << 7) + bxhi + 1]);
    for (int iy = bylo;;) {
        int nlo = 0, nhi = 0;
        if (iy < byhi) {                     // prefetch next row's bounds
            nlo = __ldg(&g_binstart[((iy + 1) << 7) + bxlo]);
            nhi = __ldg(&g_binstart[((iy + 1) << 7) + bxhi + 1]);
        }
        // prime window [W, W+PRIMEW) already handled
        scan_span(lo, min(hi, W));
        scan_span(max(lo, W + PRIMEW), hi);
        if (++iy > byhi) break;
        lo = nlo;
        hi = nhi;
    }
#undef TRY_INSERT

    // ---- final merge: per-thread lists are disjoint -> exact union top-16 ----
    merge4(kn, gmask);

    // ---- output (one writer per query): sorted distances to original row ----
    if (sub == 0) {
        const int orig = __ldg(&g_sorig[s]);
        float4* o = reinterpret_cast<float4*>(out + (size_t)orig * KNN);
        float4 r0, r1, r2, r3;
        r0.x = sqrtf(kn[0]);  r0.y = sqrtf(kn[1]);  r0.z = sqrtf(kn[2]);  r0.w = sqrtf(kn[3]);
        r1.x = sqrtf(kn[4]);  r1.y = sqrtf(kn[5]);  r1.z = sqrtf(kn[6]);  r1.w = sqrtf(kn[7]);
        r2.x = sqrtf(kn[8]);  r2.y = sqrtf(kn[9]);  r2.z = sqrtf(kn[10]); r2.w = sqrtf(kn[11]);
        r3.x = sqrtf(kn[12]); r3.y = sqrtf(kn[13]); r3.z = sqrtf(kn[14]); r3.w = sqrtf(kn[15]);
        o[0] = r0; o[1] = r1; o[2] = r2; o[3] = r3;
    }
}

extern "C" void kernel_launch(void* const* d_in, const int* in_sizes, int n_in,
                              void* d_out, int out_size) {
    const float* p = (const float*)d_in[0];
    float* out = (float*)d_out;
    int n = in_sizes[0] / 3;

    int nb = (n + 127) / 128;
    hist_kernel<<<nb, 128>>>(p, n);
    prefix_kernel<<<1, 1024>>>();
    scatter_kernel<<<nb, 128>>>(p, n);

    long long threads = (long long)TPQ * n;
    int blocks = (int)((threads + 127) / 128);
    knn4_kernel<<<blocks, 128>>>(out, n);
}